// round 4
// baseline (speedup 1.0000x reference)
#include <cuda_runtime.h>

static constexpr int N_   = 768;
static constexpr int C_M_ = 256;
static constexpr int C_Z_ = 128;
static constexpr int S_   = 128;
static constexpr int BINC = 15;

// ---------------------------------------------------------------------------
// Kernel 1: out_m[0] = m[0] + LayerNorm(m_prev[0]) * w + b
// One warp per row (256 floats -> 2 float4 per lane).
// ---------------------------------------------------------------------------
__global__ void __launch_bounds__(256) k_m0(
    const float* __restrict__ m,
    const float* __restrict__ m_prev,
    const float* __restrict__ w,
    const float* __restrict__ b,
    float* __restrict__ out)
{
    int row  = blockIdx.x * 8 + (threadIdx.x >> 5);
    int lane = threadIdx.x & 31;
    if (row >= N_) return;

    const float4* mp = reinterpret_cast<const float4*>(m_prev + (size_t)row * C_M_);
    float4 a = mp[lane];
    float4 c = mp[lane + 32];

    float s  = a.x + a.y + a.z + a.w + c.x + c.y + c.z + c.w;
    float sq = a.x*a.x + a.y*a.y + a.z*a.z + a.w*a.w
             + c.x*c.x + c.y*c.y + c.z*c.z + c.w*c.w;
#pragma unroll
    for (int o = 16; o; o >>= 1) {
        s  += __shfl_xor_sync(0xffffffffu, s,  o);
        sq += __shfl_xor_sync(0xffffffffu, sq, o);
    }
    float mu   = s  * (1.0f / C_M_);
    float var  = sq * (1.0f / C_M_) - mu * mu;
    float rinv = rsqrtf(var + 1e-5f);

    const float4* mm = reinterpret_cast<const float4*>(m + (size_t)row * C_M_);
    float4 z0 = mm[lane];
    float4 z1 = mm[lane + 32];

    int c0 = lane * 4;
    int c1 = (lane + 32) * 4;
    float4 o0, o1;
    o0.x = z0.x + (a.x - mu) * rinv * w[c0 + 0] + b[c0 + 0];
    o0.y = z0.y + (a.y - mu) * rinv * w[c0 + 1] + b[c0 + 1];
    o0.z = z0.z + (a.z - mu) * rinv * w[c0 + 2] + b[c0 + 2];
    o0.w = z0.w + (a.w - mu) * rinv * w[c0 + 3] + b[c0 + 3];
    o1.x = z1.x + (c.x - mu) * rinv * w[c1 + 0] + b[c1 + 0];
    o1.y = z1.y + (c.y - mu) * rinv * w[c1 + 1] + b[c1 + 1];
    o1.z = z1.z + (c.z - mu) * rinv * w[c1 + 2] + b[c1 + 2];
    o1.w = z1.w + (c.w - mu) * rinv * w[c1 + 3] + b[c1 + 3];

    float4* op = reinterpret_cast<float4*>(out + (size_t)row * C_M_);
    op[lane]      = o0;
    op[lane + 32] = o1;
}

// ---------------------------------------------------------------------------
// Kernel 2: copy m[1:] unchanged (float4 grid-stride)
// ---------------------------------------------------------------------------
__global__ void __launch_bounds__(256) k_copy_m(
    const float4* __restrict__ in, float4* __restrict__ out, int n4)
{
    int i      = blockIdx.x * 256 + threadIdx.x;
    int stride = gridDim.x * 256;
    for (; i < n4; i += stride) out[i] = in[i];
}

// ---------------------------------------------------------------------------
// Kernel 3: out_z[i,j,:] = z[i,j,:] + emb(bin(d_ij)) + LN(z_prev[i,j,:])
// One warp per (i,j) row (128 ch -> 1 float4 per lane).
// Shared table: 16 x 128 fused embedding (lin_w col + lin_b + ln_z_b),
// slot 15 = "no bin" (lin_b + ln_z_b only). Stored as float4 -> conflict-free.
// ---------------------------------------------------------------------------
__global__ void __launch_bounds__(256) k_z(
    const float* __restrict__ z,
    const float* __restrict__ z_prev,
    const float* __restrict__ x,
    const float* __restrict__ ln_w,
    const float* __restrict__ ln_b,
    const float* __restrict__ lin_w,
    const float* __restrict__ lin_b,
    float* __restrict__ out)
{
    __shared__ float4 s_emb[16 * 32];   // [bin][c/4]
    __shared__ float4 s_w[32];

    float* embf = reinterpret_cast<float*>(s_emb);
    float* wf   = reinterpret_cast<float*>(s_w);
    for (int t = threadIdx.x; t < 16 * C_Z_; t += 256) {
        int bb = t >> 7;          // bin index
        int c  = t & (C_Z_ - 1);  // channel
        float v = lin_b[c] + ln_b[c];
        if (bb < BINC) v += lin_w[c * BINC + bb];
        embf[t] = v;
    }
    for (int t = threadIdx.x; t < C_Z_; t += 256) wf[t] = ln_w[t];
    __syncthreads();

    int lane = threadIdx.x & 31;
    int row  = blockIdx.x * 8 + (threadIdx.x >> 5);   // exactly N*N rows launched

    int i = row / N_;
    int j = row - i * N_;

    // pairwise distance (match reference op order: (dx^2 + dy^2) + dz^2, sqrt)
    float dx = x[i * 3 + 0] - x[j * 3 + 0];
    float dy = x[i * 3 + 1] - x[j * 3 + 1];
    float dz = x[i * 3 + 2] - x[j * 3 + 2];
    float d  = sqrtf((dx * dx + dy * dy) + dz * dz);

    int bin = 15;  // "no bin" slot
#pragma unroll
    for (int bb = 0; bb < BINC; bb++) {
        float lo = 3.25f + 1.25f * (float)bb;          // exact in fp32
        float hi = (bb < BINC - 1) ? (lo + 1.25f) : 1e8f;
        if (d > lo && d < hi) bin = bb;
    }

    size_t base = (size_t)row * C_Z_;
    const float4* zr  = reinterpret_cast<const float4*>(z      + base);
    const float4* zpr = reinterpret_cast<const float4*>(z_prev + base);
    float4 zv = zr[lane];
    float4 pv = zpr[lane];

    float s  = pv.x + pv.y + pv.z + pv.w;
    float sq = pv.x*pv.x + pv.y*pv.y + pv.z*pv.z + pv.w*pv.w;
#pragma unroll
    for (int o = 16; o; o >>= 1) {
        s  += __shfl_xor_sync(0xffffffffu, s,  o);
        sq += __shfl_xor_sync(0xffffffffu, sq, o);
    }
    float mu   = s  * (1.0f / C_Z_);
    float var  = sq * (1.0f / C_Z_) - mu * mu;
    float rinv = rsqrtf(var + 1e-5f);

    float4 e  = s_emb[bin * 32 + lane];
    float4 wv = s_w[lane];

    float4 o4;
    o4.x = zv.x + e.x + (pv.x - mu) * rinv * wv.x;
    o4.y = zv.y + e.y + (pv.y - mu) * rinv * wv.y;
    o4.z = zv.z + e.z + (pv.z - mu) * rinv * wv.z;
    o4.w = zv.w + e.w + (pv.w - mu) * rinv * wv.w;

    reinterpret_cast<float4*>(out + base)[lane] = o4;
}

// ---------------------------------------------------------------------------
// Launch. Output layout: tuple (m, z) -> [m (S*N*C_M) | z (N*N*C_Z)] floats.
// Inputs (metadata order): m, z, m_prev, z_prev, x_prev,
//                          ln_m_w, ln_m_b, ln_z_w, ln_z_b, lin_w, lin_b
// ---------------------------------------------------------------------------
extern "C" void kernel_launch(void* const* d_in, const int* in_sizes, int n_in,
                              void* d_out, int out_size)
{
    const float* m      = (const float*)d_in[0];
    const float* z      = (const float*)d_in[1];
    const float* m_prev = (const float*)d_in[2];
    const float* z_prev = (const float*)d_in[3];
    const float* x_prev = (const float*)d_in[4];
    const float* ln_m_w = (const float*)d_in[5];
    const float* ln_m_b = (const float*)d_in[6];
    const float* ln_z_w = (const float*)d_in[7];
    const float* ln_z_b = (const float*)d_in[8];
    const float* lin_w  = (const float*)d_in[9];
    const float* lin_b  = (const float*)d_in[10];

    float* out_m = (float*)d_out;
    float* out_z = out_m + (size_t)S_ * N_ * C_M_;

    // m[0] += LN(m_prev[0]): 768 rows, 8 warps/block -> 96 blocks
    k_m0<<<N_ / 8, 256>>>(m, m_prev, ln_m_w, ln_m_b, out_m);

    // copy m[1:]: (S-1)*N*C_M floats
    int n4 = (S_ - 1) * N_ * C_M_ / 4;   // 6,242,304 float4
    k_copy_m<<<1184, 256>>>(
        reinterpret_cast<const float4*>(m + (size_t)N_ * C_M_),
        reinterpret_cast<float4*>(out_m + (size_t)N_ * C_M_),
        n4);

    // z: N*N rows, 8 warps/block -> 73,728 blocks (exact)
    k_z<<<(N_ * N_) / 8, 256>>>(z, z_prev, x_prev, ln_z_w, ln_z_b,
                                lin_w, lin_b, out_z);
}

// round 5
// speedup vs baseline: 1.2374x; 1.2374x over previous
#include <cuda_runtime.h>

static constexpr int N_   = 768;
static constexpr int C_M_ = 256;
static constexpr int C_Z_ = 128;
static constexpr int S_   = 128;
static constexpr int BINC = 15;

// Block partition of the single fused grid.
static constexpr int ZROWS = N_ * N_;                 // 589824 z rows
static constexpr int ZB    = ZROWS / 16;              // 2 rows/warp, 8 warps/blk -> 36864
static constexpr int CPY4  = (S_ - 1) * N_ * C_M_ / 4; // 6,242,304 float4
static constexpr int CB    = CPY4 / 1024;             // 4 float4/thread, 256 thr -> 6096 (exact)
static constexpr int MB    = N_ / 8;                  // 96 m0 blocks
static constexpr int GRID  = ZB + CB + MB;            // 43056

__global__ void __launch_bounds__(256) fused_kernel(
    const float* __restrict__ m,
    const float* __restrict__ z,
    const float* __restrict__ m_prev,
    const float* __restrict__ z_prev,
    const float* __restrict__ x,
    const float* __restrict__ ln_m_w,
    const float* __restrict__ ln_m_b,
    const float* __restrict__ ln_z_w,
    const float* __restrict__ ln_z_b,
    const float* __restrict__ lin_w,
    const float* __restrict__ lin_b,
    float* __restrict__ out_m,
    float* __restrict__ out_z)
{
    __shared__ float4 s_emb[16 * 32];   // [bin][c/4] fused emb = lin_w col + lin_b + ln_z_b
    __shared__ float4 s_w[32];          // ln_z_w

    const int bid = blockIdx.x;
    const int tid = threadIdx.x;

    if (bid < ZB) {
        // ------------------- z path: out_z = z + emb(bin(d)) + LN(z_prev) ----
        {
            float* embf = reinterpret_cast<float*>(s_emb);
            float* wf   = reinterpret_cast<float*>(s_w);
            for (int t = tid; t < 16 * C_Z_; t += 256) {
                int bb = t >> 7;
                int c  = t & (C_Z_ - 1);
                float v = lin_b[c] + ln_z_b[c];
                if (bb < BINC) v += lin_w[c * BINC + bb];
                embf[t] = v;
            }
            if (tid < C_Z_) wf[tid] = ln_z_w[tid];
        }
        __syncthreads();

        const int lane = tid & 31;
        const int gw   = bid * 8 + (tid >> 5);
        const int r0   = gw * 2;
        const int r1   = r0 + 1;

        // Front-batched loads: 4 independent 16B LDGs before any dependent math.
        size_t b0 = (size_t)r0 * C_Z_ + lane * 4;
        size_t b1 = (size_t)r1 * C_Z_ + lane * 4;
        float4 pv0 = __ldcs(reinterpret_cast<const float4*>(z_prev + b0));
        float4 pv1 = __ldcs(reinterpret_cast<const float4*>(z_prev + b1));
        float4 zv0 = __ldcs(reinterpret_cast<const float4*>(z + b0));
        float4 zv1 = __ldcs(reinterpret_cast<const float4*>(z + b1));

        // distances + bins for both rows (exact reference semantics)
        int i0 = r0 / N_, j0 = r0 - i0 * N_;
        int i1 = r1 / N_, j1 = r1 - i1 * N_;
        float dx0 = x[i0*3+0] - x[j0*3+0];
        float dy0 = x[i0*3+1] - x[j0*3+1];
        float dz0 = x[i0*3+2] - x[j0*3+2];
        float dx1 = x[i1*3+0] - x[j1*3+0];
        float dy1 = x[i1*3+1] - x[j1*3+1];
        float dz1 = x[i1*3+2] - x[j1*3+2];
        float d0 = sqrtf((dx0*dx0 + dy0*dy0) + dz0*dz0);
        float d1 = sqrtf((dx1*dx1 + dy1*dy1) + dz1*dz1);

        int bin0 = 15, bin1 = 15;
#pragma unroll
        for (int bb = 0; bb < BINC; bb++) {
            float lo = 3.25f + 1.25f * (float)bb;           // exact in fp32
            float hi = (bb < BINC - 1) ? (lo + 1.25f) : 1e8f;
            if (d0 > lo && d0 < hi) bin0 = bb;
            if (d1 > lo && d1 < hi) bin1 = bb;
        }

        // interleaved dual reductions (4 independent shuffle chains)
        float s0  = pv0.x + pv0.y + pv0.z + pv0.w;
        float q0  = pv0.x*pv0.x + pv0.y*pv0.y + pv0.z*pv0.z + pv0.w*pv0.w;
        float s1  = pv1.x + pv1.y + pv1.z + pv1.w;
        float q1  = pv1.x*pv1.x + pv1.y*pv1.y + pv1.z*pv1.z + pv1.w*pv1.w;
#pragma unroll
        for (int o = 16; o; o >>= 1) {
            s0 += __shfl_xor_sync(0xffffffffu, s0, o);
            s1 += __shfl_xor_sync(0xffffffffu, s1, o);
            q0 += __shfl_xor_sync(0xffffffffu, q0, o);
            q1 += __shfl_xor_sync(0xffffffffu, q1, o);
        }
        float mu0 = s0 * (1.0f / C_Z_);
        float mu1 = s1 * (1.0f / C_Z_);
        float r0inv = rsqrtf(q0 * (1.0f / C_Z_) - mu0 * mu0 + 1e-5f);
        float r1inv = rsqrtf(q1 * (1.0f / C_Z_) - mu1 * mu1 + 1e-5f);

        float4 e0 = s_emb[bin0 * 32 + lane];
        float4 e1 = s_emb[bin1 * 32 + lane];
        float4 wv = s_w[lane];

        float4 o0, o1;
        o0.x = zv0.x + e0.x + (pv0.x - mu0) * r0inv * wv.x;
        o0.y = zv0.y + e0.y + (pv0.y - mu0) * r0inv * wv.y;
        o0.z = zv0.z + e0.z + (pv0.z - mu0) * r0inv * wv.z;
        o0.w = zv0.w + e0.w + (pv0.w - mu0) * r0inv * wv.w;
        o1.x = zv1.x + e1.x + (pv1.x - mu1) * r1inv * wv.x;
        o1.y = zv1.y + e1.y + (pv1.y - mu1) * r1inv * wv.y;
        o1.z = zv1.z + e1.z + (pv1.z - mu1) * r1inv * wv.z;
        o1.w = zv1.w + e1.w + (pv1.w - mu1) * r1inv * wv.w;

        __stcs(reinterpret_cast<float4*>(out_z + b0), o0);
        __stcs(reinterpret_cast<float4*>(out_z + b1), o1);
    }
    else if (bid < ZB + CB) {
        // ------------------- bulk copy: m[1:] -> out_m[1:] -------------------
        const float4* in  = reinterpret_cast<const float4*>(m     + (size_t)N_ * C_M_);
        float4*       out = reinterpret_cast<float4*>(out_m + (size_t)N_ * C_M_);
        size_t base = (size_t)(bid - ZB) * 1024 + tid;
        // 4 independent front-batched LDGs
        float4 v0 = __ldcs(in + base);
        float4 v1 = __ldcs(in + base + 256);
        float4 v2 = __ldcs(in + base + 512);
        float4 v3 = __ldcs(in + base + 768);
        __stcs(out + base,       v0);
        __stcs(out + base + 256, v1);
        __stcs(out + base + 512, v2);
        __stcs(out + base + 768, v3);
    }
    else {
        // ------------------- m0: out_m[0] = m[0] + LN(m_prev[0]) -------------
        const int lane = tid & 31;
        const int row  = (bid - ZB - CB) * 8 + (tid >> 5);

        const float4* mp = reinterpret_cast<const float4*>(m_prev + (size_t)row * C_M_);
        const float4* mm = reinterpret_cast<const float4*>(m      + (size_t)row * C_M_);
        float4 a  = __ldcs(mp + lane);
        float4 c  = __ldcs(mp + lane + 32);
        float4 z0 = __ldcs(mm + lane);
        float4 z1 = __ldcs(mm + lane + 32);

        float s  = a.x + a.y + a.z + a.w + c.x + c.y + c.z + c.w;
        float sq = a.x*a.x + a.y*a.y + a.z*a.z + a.w*a.w
                 + c.x*c.x + c.y*c.y + c.z*c.z + c.w*c.w;
#pragma unroll
        for (int o = 16; o; o >>= 1) {
            s  += __shfl_xor_sync(0xffffffffu, s,  o);
            sq += __shfl_xor_sync(0xffffffffu, sq, o);
        }
        float mu   = s  * (1.0f / C_M_);
        float rinv = rsqrtf(sq * (1.0f / C_M_) - mu * mu + 1e-5f);

        int c0 = lane * 4;
        int c1 = (lane + 32) * 4;
        float4 o0, o1;
        o0.x = z0.x + (a.x - mu) * rinv * ln_m_w[c0+0] + ln_m_b[c0+0];
        o0.y = z0.y + (a.y - mu) * rinv * ln_m_w[c0+1] + ln_m_b[c0+1];
        o0.z = z0.z + (a.z - mu) * rinv * ln_m_w[c0+2] + ln_m_b[c0+2];
        o0.w = z0.w + (a.w - mu) * rinv * ln_m_w[c0+3] + ln_m_b[c0+3];
        o1.x = z1.x + (c.x - mu) * rinv * ln_m_w[c1+0] + ln_m_b[c1+0];
        o1.y = z1.y + (c.y - mu) * rinv * ln_m_w[c1+1] + ln_m_b[c1+1];
        o1.z = z1.z + (c.z - mu) * rinv * ln_m_w[c1+2] + ln_m_b[c1+2];
        o1.w = z1.w + (c.w - mu) * rinv * ln_m_w[c1+3] + ln_m_b[c1+3];

        float4* op = reinterpret_cast<float4*>(out_m + (size_t)row * C_M_);
        __stcs(op + lane,      o0);
        __stcs(op + lane + 32, o1);
    }
}

// ---------------------------------------------------------------------------
// Inputs (metadata order): m, z, m_prev, z_prev, x_prev,
//                          ln_m_w, ln_m_b, ln_z_w, ln_z_b, lin_w, lin_b
// Output: [m (S*N*C_M) | z (N*N*C_Z)] floats.
// ---------------------------------------------------------------------------
extern "C" void kernel_launch(void* const* d_in, const int* in_sizes, int n_in,
                              void* d_out, int out_size)
{
    const float* m      = (const float*)d_in[0];
    const float* z      = (const float*)d_in[1];
    const float* m_prev = (const float*)d_in[2];
    const float* z_prev = (const float*)d_in[3];
    const float* x_prev = (const float*)d_in[4];
    const float* ln_m_w = (const float*)d_in[5];
    const float* ln_m_b = (const float*)d_in[6];
    const float* ln_z_w = (const float*)d_in[7];
    const float* ln_z_b = (const float*)d_in[8];
    const float* lin_w  = (const float*)d_in[9];
    const float* lin_b  = (const float*)d_in[10];

    float* out_m = (float*)d_out;
    float* out_z = out_m + (size_t)S_ * N_ * C_M_;

    fused_kernel<<<GRID, 256>>>(m, z, m_prev, z_prev, x_prev,
                                ln_m_w, ln_m_b, ln_z_w, ln_z_b,
                                lin_w, lin_b, out_m, out_z);
}

// round 7
// speedup vs baseline: 1.3272x; 1.0726x over previous
#include <cuda_runtime.h>

static constexpr int N_   = 768;
static constexpr int C_M_ = 256;
static constexpr int C_Z_ = 128;
static constexpr int S_   = 128;
static constexpr int BINC = 15;

// Kernel A block partition: bulk copy + m0 LN + emb-table build.
static constexpr int CPY4 = (S_ - 1) * N_ * C_M_ / 4;  // 6,242,304 float4
static constexpr int CB   = CPY4 / 1024;               // 4 float4/thread -> 6096 (exact)
static constexpr int MB   = N_ / 8;                    // 96
static constexpr int GA   = CB + MB + 1;               // +1 table-build block

// Kernel B: z path, 2 rows/warp, 8 warps/block.
static constexpr int ZB   = (N_ * N_) / 16;            // 36864

// Fused embedding table: [bin 0..15][c 0..127], bin 15 = "no bin".
// entry = lin_b[c] + ln_z_b[c] + (bin<15 ? lin_w[c*15+bin] : 0)
__device__ float4 g_linT[16 * 32];

// ---------------------------------------------------------------------------
// Kernel A: m tail copy, m0 = m[0] + LN(m_prev[0]), emb table build.
// ---------------------------------------------------------------------------
__global__ void __launch_bounds__(256) kernel_a(
    const float* __restrict__ m,
    const float* __restrict__ m_prev,
    const float* __restrict__ ln_m_w,
    const float* __restrict__ ln_m_b,
    const float* __restrict__ ln_z_b,
    const float* __restrict__ lin_w,
    const float* __restrict__ lin_b,
    float* __restrict__ out_m)
{
    const int bid = blockIdx.x;
    const int tid = threadIdx.x;

    if (bid < CB) {
        // ---------------- bulk copy m[1:] -> out_m[1:] ----------------------
        const float4* in  = reinterpret_cast<const float4*>(m     + (size_t)N_ * C_M_);
        float4*       out = reinterpret_cast<float4*>(out_m + (size_t)N_ * C_M_);
        size_t base = (size_t)bid * 1024 + tid;
        float4 v0 = __ldcs(in + base);
        float4 v1 = __ldcs(in + base + 256);
        float4 v2 = __ldcs(in + base + 512);
        float4 v3 = __ldcs(in + base + 768);
        __stcs(out + base,       v0);
        __stcs(out + base + 256, v1);
        __stcs(out + base + 512, v2);
        __stcs(out + base + 768, v3);
    }
    else if (bid < CB + MB) {
        // ---------------- m0: out_m[0] = m[0] + LN(m_prev[0]) ---------------
        const int lane = tid & 31;
        const int row  = (bid - CB) * 8 + (tid >> 5);

        const float4* mp = reinterpret_cast<const float4*>(m_prev + (size_t)row * C_M_);
        const float4* mm = reinterpret_cast<const float4*>(m      + (size_t)row * C_M_);
        float4 a  = __ldcs(mp + lane);
        float4 c  = __ldcs(mp + lane + 32);
        float4 z0 = __ldcs(mm + lane);
        float4 z1 = __ldcs(mm + lane + 32);

        float s  = a.x + a.y + a.z + a.w + c.x + c.y + c.z + c.w;
        float sq = a.x*a.x + a.y*a.y + a.z*a.z + a.w*a.w
                 + c.x*c.x + c.y*c.y + c.z*c.z + c.w*c.w;
#pragma unroll
        for (int o = 16; o; o >>= 1) {
            s  += __shfl_xor_sync(0xffffffffu, s,  o);
            sq += __shfl_xor_sync(0xffffffffu, sq, o);
        }
        float mu   = s  * (1.0f / C_M_);
        float rinv = rsqrtf(sq * (1.0f / C_M_) - mu * mu + 1e-5f);

        int c0 = lane * 4;
        int c1 = (lane + 32) * 4;
        float4 o0, o1;
        o0.x = z0.x + (a.x - mu) * rinv * ln_m_w[c0+0] + ln_m_b[c0+0];
        o0.y = z0.y + (a.y - mu) * rinv * ln_m_w[c0+1] + ln_m_b[c0+1];
        o0.z = z0.z + (a.z - mu) * rinv * ln_m_w[c0+2] + ln_m_b[c0+2];
        o0.w = z0.w + (a.w - mu) * rinv * ln_m_w[c0+3] + ln_m_b[c0+3];
        o1.x = z1.x + (c.x - mu) * rinv * ln_m_w[c1+0] + ln_m_b[c1+0];
        o1.y = z1.y + (c.y - mu) * rinv * ln_m_w[c1+1] + ln_m_b[c1+1];
        o1.z = z1.z + (c.z - mu) * rinv * ln_m_w[c1+2] + ln_m_b[c1+2];
        o1.w = z1.w + (c.w - mu) * rinv * ln_m_w[c1+3] + ln_m_b[c1+3];

        float4* op = reinterpret_cast<float4*>(out_m + (size_t)row * C_M_);
        __stcs(op + lane,      o0);
        __stcs(op + lane + 32, o1);
    }
    else {
        // ---------------- build fused emb table (one block) -----------------
        float* t4 = reinterpret_cast<float*>(g_linT);
        for (int t = tid; t < 16 * C_Z_; t += 256) {
            int bb = t >> 7;
            int c  = t & (C_Z_ - 1);
            float v = lin_b[c] + ln_z_b[c];
            if (bb < BINC) v += lin_w[c * BINC + bb];
            t4[t] = v;
        }
    }
}

// ---------------------------------------------------------------------------
// Kernel B: out_z[i,j,:] = z + emb(bin(d_ij)) + LN(z_prev). 2 rows/warp.
// ---------------------------------------------------------------------------
__global__ void __launch_bounds__(256) kernel_z(
    const float* __restrict__ z,
    const float* __restrict__ z_prev,
    const float* __restrict__ x,
    const float* __restrict__ ln_z_w,
    float* __restrict__ out_z)
{
    const int tid  = threadIdx.x;
    const int lane = tid & 31;
    const int gw   = blockIdx.x * 8 + (tid >> 5);
    const int r0   = gw * 2;

    // Front-batch the bulk loads (independent, max MLP). ln_z_w joins the
    // batch so it's in flight during the reductions.
    unsigned b0 = (unsigned)r0 * C_Z_ + lane * 4;
    unsigned b1 = b0 + C_Z_;
    float4 pv0 = __ldcs(reinterpret_cast<const float4*>(z_prev + b0));
    float4 pv1 = __ldcs(reinterpret_cast<const float4*>(z_prev + b1));
    float4 zv0 = __ldcs(reinterpret_cast<const float4*>(z + b0));
    float4 zv1 = __ldcs(reinterpret_cast<const float4*>(z + b1));
    float4 wv  = __ldg(reinterpret_cast<const float4*>(ln_z_w) + lane);

    // Bin for rows r0, r0+1 computed by lanes 0,1 only (issues once/warp).
    int bin = 15;
    if (lane < 2) {
        int r = r0 + lane;
        int i = r / N_;
        int j = r - i * N_;
        float dx = x[i*3+0] - x[j*3+0];
        float dy = x[i*3+1] - x[j*3+1];
        float dz = x[i*3+2] - x[j*3+2];
        float d  = sqrtf((dx*dx + dy*dy) + dz*dz);

        // arithmetic bin estimate + exact-boundary validation over k-1..k+1
        int k = __float2int_rd((d - 3.25f) * 0.8f);
        k = max(0, min(BINC - 1, k));
#pragma unroll
        for (int u = 0; u < 3; u++) {
            int cand = k - 1 + u;
            if (cand >= 0 && cand < BINC) {
                float lo = 3.25f + 1.25f * (float)cand;             // exact fp32
                float hi = (cand < BINC - 1) ? (lo + 1.25f) : 1e8f;
                if (d > lo && d < hi) bin = cand;
            }
        }
    }
    int bin0 = __shfl_sync(0xffffffffu, bin, 0);
    int bin1 = __shfl_sync(0xffffffffu, bin, 1);

    // LN stats, dual interleaved shuffle reductions.
    float s0 = pv0.x + pv0.y + pv0.z + pv0.w;
    float q0 = pv0.x*pv0.x + pv0.y*pv0.y + pv0.z*pv0.z + pv0.w*pv0.w;
    float s1 = pv1.x + pv1.y + pv1.z + pv1.w;
    float q1 = pv1.x*pv1.x + pv1.y*pv1.y + pv1.z*pv1.z + pv1.w*pv1.w;
#pragma unroll
    for (int o = 16; o; o >>= 1) {
        s0 += __shfl_xor_sync(0xffffffffu, s0, o);
        s1 += __shfl_xor_sync(0xffffffffu, s1, o);
        q0 += __shfl_xor_sync(0xffffffffu, q0, o);
        q1 += __shfl_xor_sync(0xffffffffu, q1, o);
    }
    float mu0 = s0 * (1.0f / C_Z_);
    float mu1 = s1 * (1.0f / C_Z_);
    float ri0 = rsqrtf(q0 * (1.0f / C_Z_) - mu0 * mu0 + 1e-5f);
    float ri1 = rsqrtf(q1 * (1.0f / C_Z_) - mu1 * mu1 + 1e-5f);

    // Coalesced fused-emb rows (L1/L2-resident).
    float4 e0 = g_linT[bin0 * 32 + lane];
    float4 e1 = g_linT[bin1 * 32 + lane];

    float4 o0, o1;
    o0.x = zv0.x + e0.x + (pv0.x - mu0) * ri0 * wv.x;
    o0.y = zv0.y + e0.y + (pv0.y - mu0) * ri0 * wv.y;
    o0.z = zv0.z + e0.z + (pv0.z - mu0) * ri0 * wv.z;
    o0.w = zv0.w + e0.w + (pv0.w - mu0) * ri0 * wv.w;
    o1.x = zv1.x + e1.x + (pv1.x - mu1) * ri1 * wv.x;
    o1.y = zv1.y + e1.y + (pv1.y - mu1) * ri1 * wv.y;
    o1.z = zv1.z + e1.z + (pv1.z - mu1) * ri1 * wv.z;
    o1.w = zv1.w + e1.w + (pv1.w - mu1) * ri1 * wv.w;

    __stcs(reinterpret_cast<float4*>(out_z + b0), o0);
    __stcs(reinterpret_cast<float4*>(out_z + b1), o1);
}

// ---------------------------------------------------------------------------
// Inputs (metadata order): m, z, m_prev, z_prev, x_prev,
//                          ln_m_w, ln_m_b, ln_z_w, ln_z_b, lin_w, lin_b
// Output: [m (S*N*C_M) | z (N*N*C_Z)] floats.
// ---------------------------------------------------------------------------
extern "C" void kernel_launch(void* const* d_in, const int* in_sizes, int n_in,
                              void* d_out, int out_size)
{
    const float* m      = (const float*)d_in[0];
    const float* z      = (const float*)d_in[1];
    const float* m_prev = (const float*)d_in[2];
    const float* z_prev = (const float*)d_in[3];
    const float* x_prev = (const float*)d_in[4];
    const float* ln_m_w = (const float*)d_in[5];
    const float* ln_m_b = (const float*)d_in[6];
    const float* ln_z_w = (const float*)d_in[7];
    const float* ln_z_b = (const float*)d_in[8];
    const float* lin_w  = (const float*)d_in[9];
    const float* lin_b  = (const float*)d_in[10];

    float* out_m = (float*)d_out;
    float* out_z = out_m + (size_t)S_ * N_ * C_M_;

    // A: m copy + m0 LN + emb-table build (table build hidden under bulk copy)
    kernel_a<<<GA, 256>>>(m, m_prev, ln_m_w, ln_m_b, ln_z_b, lin_w, lin_b, out_m);
    // B: z path (reads g_linT; stream order guarantees visibility)
    kernel_z<<<ZB, 256>>>(z, z_prev, x_prev, ln_z_w, out_z);
}